// round 3
// baseline (speedup 1.0000x reference)
#include <cuda_runtime.h>
#include <math.h>

// Problem dims
#define TB   262144   // T*B = 256*1024
#define TT   256
#define BB   1024
#define HH   128
#define LSZ  128
#define OBS  128
#define NOUT 19

// ---------------- scratch (static device memory; no allocs) ----------------
__device__ float g_h1[TB * 128];        // 128 MB
__device__ float g_h2[TB * 32];         //  32 MB
__device__ float g_h3[TB * 128];        // 128 MB
__device__ float g_xg[TB * 512];        // 512 MB  (precomputed x-gates + biases)
__device__ float g_hs[TB * 128];        // 128 MB  (LSTM hidden outputs)
__device__ float g_WhhT[128 * 512];     // transposed recurrent weights [k][n]
__device__ float g_bg[512];             // bih + bhh
__device__ float g_Whead[NOUT * 128];   // [Wa; Wc]
__device__ float g_bhead[NOUT];         // [ba; bc]

// ---------------- fast activations ----------------
__device__ __forceinline__ float sigmoid_f(float x) {
    return __fdividef(1.f, 1.f + __expf(-x));
}
__device__ __forceinline__ float tanh_f(float x) {
    float e = __expf(-2.f * fabsf(x));          // in (0,1], no overflow
    float r = __fdividef(1.f - e, 1.f + e);
    return copysignf(r, x);
}

// ---------------- prepack: WhhT, fused biases, head weights ----------------
__global__ void prepack_kernel(const float* __restrict__ Whh,
                               const float* __restrict__ bih,
                               const float* __restrict__ bhh,
                               const float* __restrict__ Wa,
                               const float* __restrict__ ba,
                               const float* __restrict__ Wc,
                               const float* __restrict__ bc) {
    int t = blockIdx.x * blockDim.x + threadIdx.x;
    int stride = gridDim.x * blockDim.x;
    // WhhT[k][n] = Whh[n][k]
    for (int i = t; i < 128 * 512; i += stride) {
        int k = i / 512, n = i % 512;
        g_WhhT[i] = Whh[n * 128 + k];
    }
    if (t < 512) g_bg[t] = bih[t] + bhh[t];
    for (int i = t; i < NOUT * 128; i += stride) {
        int n = i / 128, k = i % 128;
        g_Whead[i] = (n < 18) ? Wa[n * 128 + k] : Wc[k];
    }
    if (t < NOUT) g_bhead[t] = (t < 18) ? ba[t] : bc[0];
}

// ---------------- generic SGEMM: C = act(A[M,K] @ W[N,K]^T + bias) ----------------
template<int BM, int BN, int BK, int TM, int TN, bool RELU, bool NGUARD>
__global__ void __launch_bounds__((BM / TM) * (BN / TN))
gemm_kernel(const float* __restrict__ A, const float* __restrict__ W,
            const float* __restrict__ bias, float* __restrict__ C,
            int N, int K, int ldc) {
    constexpr int THREADS = (BM / TM) * (BN / TN);
    constexpr int BNQ = BN / TN;
    __shared__ float As[BK][BM + 4];
    __shared__ float Ws[BK][BN + 4];

    const int tid = threadIdx.x;
    const int bm = blockIdx.x * BM;
    const int bn = blockIdx.y * BN;
    const int tx = tid % BNQ;
    const int ty = tid / BNQ;

    float acc[TM][TN];
#pragma unroll
    for (int i = 0; i < TM; i++)
#pragma unroll
        for (int j = 0; j < TN; j++) acc[i][j] = 0.f;

    for (int k0 = 0; k0 < K; k0 += BK) {
        // A tile (BM x BK), float4 loads, store transposed
        constexpr int AV = BM * BK / 4;
        constexpr int AIT = AV / THREADS;
#pragma unroll
        for (int i = 0; i < AIT; i++) {
            int idx = tid + i * THREADS;
            int row = idx / (BK / 4);
            int c4 = idx % (BK / 4);
            float4 v = *(const float4*)(A + (size_t)(bm + row) * K + k0 + c4 * 4);
            As[c4 * 4 + 0][row] = v.x;
            As[c4 * 4 + 1][row] = v.y;
            As[c4 * 4 + 2][row] = v.z;
            As[c4 * 4 + 3][row] = v.w;
        }
        // W tile (BN x BK)
        constexpr int WV = BN * BK / 4;
        constexpr int WIT = (WV + THREADS - 1) / THREADS;
#pragma unroll
        for (int i = 0; i < WIT; i++) {
            int idx = tid + i * THREADS;
            if ((WV % THREADS == 0) || idx < WV) {
                int row = idx / (BK / 4);
                int c4 = idx % (BK / 4);
                float4 v;
                if (!NGUARD || (bn + row) < N)
                    v = *(const float4*)(W + (size_t)(bn + row) * K + k0 + c4 * 4);
                else
                    v = make_float4(0.f, 0.f, 0.f, 0.f);
                Ws[c4 * 4 + 0][row] = v.x;
                Ws[c4 * 4 + 1][row] = v.y;
                Ws[c4 * 4 + 2][row] = v.z;
                Ws[c4 * 4 + 3][row] = v.w;
            }
        }
        __syncthreads();
#pragma unroll
        for (int kk = 0; kk < BK; kk++) {
            float a[TM], b[TN];
#pragma unroll
            for (int i = 0; i < TM; i++) a[i] = As[kk][ty * TM + i];
#pragma unroll
            for (int j = 0; j < TN; j++) b[j] = Ws[kk][tx * TN + j];
#pragma unroll
            for (int i = 0; i < TM; i++)
#pragma unroll
                for (int j = 0; j < TN; j++) acc[i][j] += a[i] * b[j];
        }
        __syncthreads();
    }
    // epilogue
#pragma unroll
    for (int j = 0; j < TN; j++) {
        int n = bn + tx * TN + j;
        if (NGUARD && n >= N) continue;
        float bv = bias[n];
#pragma unroll
        for (int i = 0; i < TM; i++) {
            float v = acc[i][j] + bv;
            if (RELU) v = fmaxf(v, 0.f);
            C[(size_t)(bm + ty * TM + i) * ldc + n] = v;
        }
    }
}

// ---------------- persistent LSTM recurrence ----------------
// grid = 128 CTAs, 512 threads. Each CTA owns 8 batch rows for all 256 steps.
// Thread t computes gate output n = t for all 8 rows (8x512x128 matvec per step),
// then 1024 cell updates are spread 2-per-thread.
__global__ void __launch_bounds__(512, 1)
lstm_kernel(const float* __restrict__ xg, const float* __restrict__ done,
            const float* __restrict__ h0, const float* __restrict__ c0,
            float* __restrict__ hs, const float* __restrict__ WT) {
    __shared__ float h_s[128][8];      // [k][b]
    __shared__ float gates_s[8][512];  // [b][n]

    const int t = threadIdx.x;
    const int b0 = blockIdx.x * 8;
    const int n = t;

    // cell-pair ownership: pair0 -> batches 0..3, pair1 -> batches 4..7
    const int bp0 = t >> 7;
    const int bp1 = 4 + (t >> 7);
    const int jp = t & 127;

    float c_r0 = c0[(b0 + bp0) * 128 + jp];
    float c_r1 = c0[(b0 + bp1) * 128 + jp];
    h_s[jp][bp0] = h0[(b0 + bp0) * 128 + jp];
    h_s[jp][bp1] = h0[(b0 + bp1) * 128 + jp];
    __syncthreads();

    for (int step = 0; step < TT; ++step) {
        // reset mask (done applies at start of step)
        float m0 = 1.f - done[step * BB + b0 + bp0];
        float m1 = 1.f - done[step * BB + b0 + bp1];
        c_r0 *= m0;
        c_r1 *= m1;
        h_s[jp][bp0] *= m0;   // each entry owned by exactly one thread
        h_s[jp][bp1] *= m1;
        __syncthreads();

        // prefetch x-gates for this thread's 8 batch rows
        float xr[8];
        const float* xgp = xg + (size_t)(step * BB + b0) * 512 + n;
#pragma unroll
        for (int b = 0; b < 8; b++) xr[b] = xgp[b * 512];

        // matvec: acc[b] = sum_k Whh[n][k] * h[b][k]
        float acc[8];
#pragma unroll
        for (int b = 0; b < 8; b++) acc[b] = 0.f;
#pragma unroll 8
        for (int k = 0; k < 128; k++) {
            float w = WT[k * 512 + n];
            float4 ha = *(const float4*)&h_s[k][0];
            float4 hb = *(const float4*)&h_s[k][4];
            acc[0] += w * ha.x; acc[1] += w * ha.y;
            acc[2] += w * ha.z; acc[3] += w * ha.w;
            acc[4] += w * hb.x; acc[5] += w * hb.y;
            acc[6] += w * hb.z; acc[7] += w * hb.w;
        }

        // activation (gate order [i,f,g,o]; g (256..383) uses tanh) — uniform per warp
        const bool use_sig = (n < 256) || (n >= 384);
#pragma unroll
        for (int b = 0; b < 8; b++) {
            float v = acc[b] + xr[b];
            gates_s[b][n] = use_sig ? sigmoid_f(v) : tanh_f(v);
        }
        __syncthreads();

        // cell update: 1024 (b,j) pairs, 2 per thread
        {
            float i0 = gates_s[bp0][jp];
            float f0 = gates_s[bp0][jp + 128];
            float g0 = gates_s[bp0][jp + 256];
            float o0 = gates_s[bp0][jp + 384];
            c_r0 = f0 * c_r0 + i0 * g0;
            float hh0 = o0 * tanh_f(c_r0);

            float i1 = gates_s[bp1][jp];
            float f1 = gates_s[bp1][jp + 128];
            float g1 = gates_s[bp1][jp + 256];
            float o1 = gates_s[bp1][jp + 384];
            c_r1 = f1 * c_r1 + i1 * g1;
            float hh1 = o1 * tanh_f(c_r1);

            h_s[jp][bp0] = hh0;
            h_s[jp][bp1] = hh1;
            hs[(size_t)(step * BB + b0 + bp0) * 128 + jp] = hh0;
            hs[(size_t)(step * BB + b0 + bp1) * 128 + jp] = hh1;
        }
        __syncthreads();
    }
}

// ---------------- launch ----------------
extern "C" void kernel_launch(void* const* d_in, const int* in_sizes, int n_in,
                              void* d_out, int out_size) {
    const float* x    = (const float*)d_in[0];
    const float* done = (const float*)d_in[1];
    const float* h0   = (const float*)d_in[2];
    const float* c0   = (const float*)d_in[3];
    const float* W1   = (const float*)d_in[4];
    const float* b1   = (const float*)d_in[5];
    const float* W2   = (const float*)d_in[6];
    const float* b2   = (const float*)d_in[7];
    const float* W3   = (const float*)d_in[8];
    const float* b3   = (const float*)d_in[9];
    const float* Wih  = (const float*)d_in[10];
    const float* Whh  = (const float*)d_in[11];
    const float* bih  = (const float*)d_in[12];
    const float* bhh  = (const float*)d_in[13];
    const float* Wa   = (const float*)d_in[14];
    const float* ba   = (const float*)d_in[15];
    const float* Wc   = (const float*)d_in[16];
    const float* bc   = (const float*)d_in[17];
    float* out = (float*)d_out;

    float *h1, *h2, *h3, *xgp, *hsp, *whhT, *bg, *whd, *bhd;
    cudaGetSymbolAddress((void**)&h1,   g_h1);
    cudaGetSymbolAddress((void**)&h2,   g_h2);
    cudaGetSymbolAddress((void**)&h3,   g_h3);
    cudaGetSymbolAddress((void**)&xgp,  g_xg);
    cudaGetSymbolAddress((void**)&hsp,  g_hs);
    cudaGetSymbolAddress((void**)&whhT, g_WhhT);
    cudaGetSymbolAddress((void**)&bg,   g_bg);
    cudaGetSymbolAddress((void**)&whd,  g_Whead);
    cudaGetSymbolAddress((void**)&bhd,  g_bhead);

    prepack_kernel<<<128, 256>>>(Whh, bih, bhh, Wa, ba, Wc, bc);

    // MLP encoder
    gemm_kernel<128, 128, 32, 8, 8, true, false>
        <<<dim3(TB / 128, 1), 256>>>(x, W1, b1, h1, 128, 128, 128);
    gemm_kernel<128, 32, 32, 8, 2, true, false>
        <<<dim3(TB / 128, 1), 256>>>(h1, W2, b2, h2, 32, 128, 32);
    gemm_kernel<128, 128, 32, 8, 8, true, false>
        <<<dim3(TB / 128, 1), 256>>>(h2, W3, b3, h3, 128, 32, 128);

    // Precompute x-side gate contributions with fused biases: xg = h3 @ Wih^T + (bih+bhh)
    gemm_kernel<128, 128, 32, 8, 8, false, false>
        <<<dim3(TB / 128, 4), 256>>>(h3, Wih, bg, xgp, 512, 128, 512);

    // Sequential LSTM (batch-parallel, persistent over 256 steps)
    lstm_kernel<<<128, 512>>>(xgp, done, h0, c0, hsp, whhT);

    // Heads: out = [hs @ Wa^T + ba, hs @ Wc^T + bc]
    gemm_kernel<128, 32, 32, 8, 2, false, true>
        <<<dim3(TB / 128, 1), 256>>>(hsp, whd, bhd, out, NOUT, 128, NOUT);
}

// round 4
// speedup vs baseline: 1.0633x; 1.0633x over previous
#include <cuda_runtime.h>
#include <math.h>

// Problem dims
#define TB   262144   // T*B = 256*1024
#define TT   256
#define BB   1024
#define HH   128
#define LSZ  128
#define OBS  128
#define NOUT 19

// ---------------- scratch (static device memory; no allocs) ----------------
__device__ float g_h1[TB * 128];
__device__ float g_h2[TB * 32];
__device__ float g_h3[TB * 128];
__device__ float g_xg[TB * 512];
__device__ float g_hs[TB * 128];
__device__ float g_WhhT[128 * 512];     // [k][n]
__device__ float g_bg[512];
__device__ float g_Whead[NOUT * 128];
__device__ float g_bhead[NOUT];

// ---------------- packed f32x2 helpers ----------------
typedef unsigned long long ull;
__device__ __forceinline__ ull pack2(float lo, float hi) {
    ull r; asm("mov.b64 %0, {%1, %2};" : "=l"(r) : "f"(lo), "f"(hi)); return r;
}
__device__ __forceinline__ void unpack2(ull p, float& lo, float& hi) {
    asm("mov.b64 {%0, %1}, %2;" : "=f"(lo), "=f"(hi) : "l"(p));
}
__device__ __forceinline__ ull ffma2(ull a, ull b, ull c) {
    ull d; asm("fma.rn.f32x2 %0, %1, %2, %3;" : "=l"(d) : "l"(a), "l"(b), "l"(c));
    return d;
}
__device__ __forceinline__ ull d_as_u(double d) { return __double_as_longlong(d); }

// ---------------- fast activations ----------------
__device__ __forceinline__ float sigmoid_f(float x) {
    return __fdividef(1.f, 1.f + __expf(-x));
}
__device__ __forceinline__ float tanh_f(float x) {
    float e = __expf(-2.f * fabsf(x));
    float r = __fdividef(1.f - e, 1.f + e);
    return copysignf(r, x);
}

// ---------------- prepack ----------------
__global__ void prepack_kernel(const float* __restrict__ Whh,
                               const float* __restrict__ bih,
                               const float* __restrict__ bhh,
                               const float* __restrict__ Wa,
                               const float* __restrict__ ba,
                               const float* __restrict__ Wc,
                               const float* __restrict__ bc) {
    int t = blockIdx.x * blockDim.x + threadIdx.x;
    int stride = gridDim.x * blockDim.x;
    for (int i = t; i < 128 * 512; i += stride) {
        int k = i / 512, n = i % 512;
        g_WhhT[i] = Whh[n * 128 + k];
    }
    if (t < 512) g_bg[t] = bih[t] + bhh[t];
    for (int i = t; i < NOUT * 128; i += stride) {
        int n = i / 128, k = i % 128;
        g_Whead[i] = (n < 18) ? Wa[n * 128 + k] : Wc[k];
    }
    if (t < NOUT) g_bhead[t] = (t < 18) ? ba[t] : bc[0];
}

// ---------------- SGEMM with f32x2: C = act(A[M,K] @ W[N,K]^T + bias) ----------------
template<int BM, int BN, int BK, int TM, int TN, bool RELU, bool NGUARD>
__global__ void __launch_bounds__((BM / TM) * (BN / TN))
gemm_kernel(const float* __restrict__ A, const float* __restrict__ W,
            const float* __restrict__ bias, float* __restrict__ C,
            int N, int K, int ldc) {
    constexpr int THREADS = (BM / TM) * (BN / TN);
    constexpr int BNQ = BN / TN;
    static_assert(TM % 2 == 0, "TM even for f32x2 pairing");
    __shared__ __align__(16) float As[BK][BM + 4];
    __shared__ __align__(16) float Ws[BK][BN + 4];

    const int tid = threadIdx.x;
    const int bm = blockIdx.x * BM;
    const int bn = blockIdx.y * BN;
    const int tx = tid % BNQ;
    const int ty = tid / BNQ;

    // accumulators paired along M: acc2[i2][j] holds rows (2*i2, 2*i2+1)
    ull acc2[TM / 2][TN];
#pragma unroll
    for (int i = 0; i < TM / 2; i++)
#pragma unroll
        for (int j = 0; j < TN; j++) acc2[i][j] = 0ull;

    for (int k0 = 0; k0 < K; k0 += BK) {
        constexpr int AV = BM * BK / 4;
        constexpr int AIT = AV / THREADS;
#pragma unroll
        for (int i = 0; i < AIT; i++) {
            int idx = tid + i * THREADS;
            int row = idx / (BK / 4);
            int c4 = idx % (BK / 4);
            float4 v = *(const float4*)(A + (size_t)(bm + row) * K + k0 + c4 * 4);
            As[c4 * 4 + 0][row] = v.x;
            As[c4 * 4 + 1][row] = v.y;
            As[c4 * 4 + 2][row] = v.z;
            As[c4 * 4 + 3][row] = v.w;
        }
        constexpr int WV = BN * BK / 4;
        constexpr int WIT = (WV + THREADS - 1) / THREADS;
#pragma unroll
        for (int i = 0; i < WIT; i++) {
            int idx = tid + i * THREADS;
            if ((WV % THREADS == 0) || idx < WV) {
                int row = idx / (BK / 4);
                int c4 = idx % (BK / 4);
                float4 v;
                if (!NGUARD || (bn + row) < N)
                    v = *(const float4*)(W + (size_t)(bn + row) * K + k0 + c4 * 4);
                else
                    v = make_float4(0.f, 0.f, 0.f, 0.f);
                Ws[c4 * 4 + 0][row] = v.x;
                Ws[c4 * 4 + 1][row] = v.y;
                Ws[c4 * 4 + 2][row] = v.z;
                Ws[c4 * 4 + 3][row] = v.w;
            }
        }
        __syncthreads();
#pragma unroll
        for (int kk = 0; kk < BK; kk++) {
            // a: TM/2 ready-made pairs from shared (16B aligned: ty*TM*4 % 8 == 0)
            ull a2[TM / 2];
#pragma unroll
            for (int i2 = 0; i2 < TM / 2; i2++)
                a2[i2] = *(const ull*)&As[kk][ty * TM + 2 * i2];
            // b: scalars, duplicated into both halves
            float br[TN];
            if constexpr (TN % 4 == 0) {
#pragma unroll
                for (int j4 = 0; j4 < TN / 4; j4++) {
                    float4 v = *(const float4*)&Ws[kk][tx * TN + 4 * j4];
                    br[4 * j4 + 0] = v.x; br[4 * j4 + 1] = v.y;
                    br[4 * j4 + 2] = v.z; br[4 * j4 + 3] = v.w;
                }
            } else {
#pragma unroll
                for (int j = 0; j < TN; j++) br[j] = Ws[kk][tx * TN + j];
            }
            ull b2[TN];
#pragma unroll
            for (int j = 0; j < TN; j++) b2[j] = pack2(br[j], br[j]);
#pragma unroll
            for (int i2 = 0; i2 < TM / 2; i2++)
#pragma unroll
                for (int j = 0; j < TN; j++)
                    acc2[i2][j] = ffma2(a2[i2], b2[j], acc2[i2][j]);
        }
        __syncthreads();
    }
    // epilogue
#pragma unroll
    for (int j = 0; j < TN; j++) {
        int n = bn + tx * TN + j;
        if (NGUARD && n >= N) continue;
        float bv = bias[n];
#pragma unroll
        for (int i2 = 0; i2 < TM / 2; i2++) {
            float v0, v1;
            unpack2(acc2[i2][j], v0, v1);
            v0 += bv; v1 += bv;
            if (RELU) { v0 = fmaxf(v0, 0.f); v1 = fmaxf(v1, 0.f); }
            C[(size_t)(bm + ty * TM + 2 * i2 + 0) * ldc + n] = v0;
            C[(size_t)(bm + ty * TM + 2 * i2 + 1) * ldc + n] = v1;
        }
    }
}

// ---------------- persistent LSTM recurrence (f32x2 matvec) ----------------
// 128 CTAs x 512 threads; CTA owns 8 batch rows for all 256 steps.
__global__ void __launch_bounds__(512, 1)
lstm_kernel(const float* __restrict__ xg, const float* __restrict__ done,
            const float* __restrict__ h0, const float* __restrict__ c0,
            float* __restrict__ hs, const float* __restrict__ WT) {
    __shared__ __align__(16) float h_s[128][8];   // [k][b]
    __shared__ float gates_s[8][512];             // [b][n]

    const int t = threadIdx.x;
    const int b0 = blockIdx.x * 8;
    const int n = t;

    const int bp0 = t >> 7;
    const int bp1 = 4 + (t >> 7);
    const int jp = t & 127;

    float c_r0 = c0[(b0 + bp0) * 128 + jp];
    float c_r1 = c0[(b0 + bp1) * 128 + jp];
    h_s[jp][bp0] = h0[(b0 + bp0) * 128 + jp];
    h_s[jp][bp1] = h0[(b0 + bp1) * 128 + jp];
    __syncthreads();

    for (int step = 0; step < TT; ++step) {
        float m0 = 1.f - done[step * BB + b0 + bp0];
        float m1 = 1.f - done[step * BB + b0 + bp1];
        c_r0 *= m0;
        c_r1 *= m1;
        h_s[jp][bp0] *= m0;
        h_s[jp][bp1] *= m1;
        __syncthreads();

        // prefetch x-gates for this thread's 8 batch rows
        float xr[8];
        const float* xgp = xg + (size_t)(step * BB + b0) * 512 + n;
#pragma unroll
        for (int b = 0; b < 8; b++) xr[b] = xgp[b * 512];

        // matvec: packed pairs along batch. acc2[p] = (sum for b=2p, b=2p+1)
        ull acc2[4];
#pragma unroll
        for (int p = 0; p < 4; p++) acc2[p] = 0ull;
#pragma unroll 8
        for (int k = 0; k < 128; k++) {
            float w = WT[k * 512 + n];
            ull w2 = pack2(w, w);
            double2 hA = *(const double2*)&h_s[k][0];   // (b0,b1),(b2,b3)
            double2 hB = *(const double2*)&h_s[k][4];   // (b4,b5),(b6,b7)
            acc2[0] = ffma2(w2, d_as_u(hA.x), acc2[0]);
            acc2[1] = ffma2(w2, d_as_u(hA.y), acc2[1]);
            acc2[2] = ffma2(w2, d_as_u(hB.x), acc2[2]);
            acc2[3] = ffma2(w2, d_as_u(hB.y), acc2[3]);
        }
        float acc[8];
#pragma unroll
        for (int p = 0; p < 4; p++) unpack2(acc2[p], acc[2 * p], acc[2 * p + 1]);

        // activation (gate order [i,f,g,o]; g (256..383) uses tanh) — uniform per warp
        const bool use_sig = (n < 256) || (n >= 384);
#pragma unroll
        for (int b = 0; b < 8; b++) {
            float v = acc[b] + xr[b];
            gates_s[b][n] = use_sig ? sigmoid_f(v) : tanh_f(v);
        }
        __syncthreads();

        // cell update: 1024 (b,j) pairs, 2 per thread
        {
            float i0 = gates_s[bp0][jp];
            float f0 = gates_s[bp0][jp + 128];
            float g0 = gates_s[bp0][jp + 256];
            float o0 = gates_s[bp0][jp + 384];
            c_r0 = f0 * c_r0 + i0 * g0;
            float hh0 = o0 * tanh_f(c_r0);

            float i1 = gates_s[bp1][jp];
            float f1 = gates_s[bp1][jp + 128];
            float g1 = gates_s[bp1][jp + 256];
            float o1 = gates_s[bp1][jp + 384];
            c_r1 = f1 * c_r1 + i1 * g1;
            float hh1 = o1 * tanh_f(c_r1);

            h_s[jp][bp0] = hh0;
            h_s[jp][bp1] = hh1;
            hs[(size_t)(step * BB + b0 + bp0) * 128 + jp] = hh0;
            hs[(size_t)(step * BB + b0 + bp1) * 128 + jp] = hh1;
        }
        __syncthreads();
    }
}

// ---------------- launch ----------------
extern "C" void kernel_launch(void* const* d_in, const int* in_sizes, int n_in,
                              void* d_out, int out_size) {
    const float* x    = (const float*)d_in[0];
    const float* done = (const float*)d_in[1];
    const float* h0   = (const float*)d_in[2];
    const float* c0   = (const float*)d_in[3];
    const float* W1   = (const float*)d_in[4];
    const float* b1   = (const float*)d_in[5];
    const float* W2   = (const float*)d_in[6];
    const float* b2   = (const float*)d_in[7];
    const float* W3   = (const float*)d_in[8];
    const float* b3   = (const float*)d_in[9];
    const float* Wih  = (const float*)d_in[10];
    const float* Whh  = (const float*)d_in[11];
    const float* bih  = (const float*)d_in[12];
    const float* bhh  = (const float*)d_in[13];
    const float* Wa   = (const float*)d_in[14];
    const float* ba   = (const float*)d_in[15];
    const float* Wc   = (const float*)d_in[16];
    const float* bc   = (const float*)d_in[17];
    float* out = (float*)d_out;

    float *h1, *h2, *h3, *xgp, *hsp, *whhT, *bg, *whd, *bhd;
    cudaGetSymbolAddress((void**)&h1,   g_h1);
    cudaGetSymbolAddress((void**)&h2,   g_h2);
    cudaGetSymbolAddress((void**)&h3,   g_h3);
    cudaGetSymbolAddress((void**)&xgp,  g_xg);
    cudaGetSymbolAddress((void**)&hsp,  g_hs);
    cudaGetSymbolAddress((void**)&whhT, g_WhhT);
    cudaGetSymbolAddress((void**)&bg,   g_bg);
    cudaGetSymbolAddress((void**)&whd,  g_Whead);
    cudaGetSymbolAddress((void**)&bhd,  g_bhead);

    prepack_kernel<<<128, 256>>>(Whh, bih, bhh, Wa, ba, Wc, bc);

    // MLP encoder
    gemm_kernel<128, 128, 32, 8, 8, true, false>
        <<<dim3(TB / 128, 1), 256>>>(x, W1, b1, h1, 128, 128, 128);
    gemm_kernel<128, 32, 32, 8, 2, true, false>
        <<<dim3(TB / 128, 1), 256>>>(h1, W2, b2, h2, 32, 128, 32);
    gemm_kernel<128, 128, 32, 8, 8, true, false>
        <<<dim3(TB / 128, 1), 256>>>(h2, W3, b3, h3, 128, 32, 128);

    // xg = h3 @ Wih^T + (bih+bhh)
    gemm_kernel<128, 128, 32, 8, 8, false, false>
        <<<dim3(TB / 128, 4), 256>>>(h3, Wih, bg, xgp, 512, 128, 512);

    // Sequential LSTM
    lstm_kernel<<<128, 512>>>(xgp, done, h0, c0, hsp, whhT);

    // Heads
    gemm_kernel<128, 32, 32, 8, 2, false, true>
        <<<dim3(TB / 128, 1), 256>>>(hsp, whd, bhd, out, NOUT, 128, NOUT);
}

// round 5
// speedup vs baseline: 1.3722x; 1.2906x over previous
#include <cuda_runtime.h>
#include <math.h>

// Problem dims
#define TB   262144   // T*B = 256*1024
#define TT   256
#define BB   1024
#define HH   128
#define NOUT 19

// ---------------- scratch (static device memory; no allocs) ----------------
__device__ float g_h1[TB * 128];
__device__ float g_h2[TB * 32];
__device__ float g_h3[TB * 128];
__device__ float g_xg[TB * 512];
__device__ float g_hs[TB * 128];
__device__ float g_WhhT[128 * 512];     // [k][n]
__device__ float g_bg[512];
__device__ float g_Whead[NOUT * 128];
__device__ float g_bhead[NOUT];

// ---------------- packed f32x2 helpers (LSTM) ----------------
typedef unsigned long long ull;
__device__ __forceinline__ ull pack2(float lo, float hi) {
    ull r; asm("mov.b64 %0, {%1, %2};" : "=l"(r) : "f"(lo), "f"(hi)); return r;
}
__device__ __forceinline__ void unpack2(ull p, float& lo, float& hi) {
    asm("mov.b64 {%0, %1}, %2;" : "=f"(lo), "=f"(hi) : "l"(p));
}
__device__ __forceinline__ ull ffma2(ull a, ull b, ull c) {
    ull d; asm("fma.rn.f32x2 %0, %1, %2, %3;" : "=l"(d) : "l"(a), "l"(b), "l"(c));
    return d;
}
__device__ __forceinline__ ull d_as_u(double d) { return __double_as_longlong(d); }

// ---------------- tf32 helpers ----------------
__device__ __forceinline__ unsigned tf32_of(float f) {
    unsigned r; asm("cvt.rna.tf32.f32 %0, %1;" : "=r"(r) : "f"(f)); return r;
}
__device__ __forceinline__ void mma_tf32(float* d, const unsigned* a, const unsigned* b) {
    asm volatile(
        "mma.sync.aligned.m16n8k8.row.col.f32.tf32.tf32.f32 "
        "{%0,%1,%2,%3}, {%4,%5,%6,%7}, {%8,%9}, {%0,%1,%2,%3};"
        : "+f"(d[0]), "+f"(d[1]), "+f"(d[2]), "+f"(d[3])
        : "r"(a[0]), "r"(a[1]), "r"(a[2]), "r"(a[3]), "r"(b[0]), "r"(b[1]));
}

// ---------------- fast activations ----------------
__device__ __forceinline__ float sigmoid_f(float x) {
    return __fdividef(1.f, 1.f + __expf(-x));
}
__device__ __forceinline__ float tanh_f(float x) {
    float e = __expf(-2.f * fabsf(x));
    float r = __fdividef(1.f - e, 1.f + e);
    return copysignf(r, x);
}

// ---------------- prepack ----------------
__global__ void prepack_kernel(const float* __restrict__ Whh,
                               const float* __restrict__ bih,
                               const float* __restrict__ bhh,
                               const float* __restrict__ Wa,
                               const float* __restrict__ ba,
                               const float* __restrict__ Wc,
                               const float* __restrict__ bc) {
    int t = blockIdx.x * blockDim.x + threadIdx.x;
    int stride = gridDim.x * blockDim.x;
    for (int i = t; i < 128 * 512; i += stride) {
        int k = i / 512, n = i % 512;
        g_WhhT[i] = Whh[n * 128 + k];
    }
    if (t < 512) g_bg[t] = bih[t] + bhh[t];
    for (int i = t; i < NOUT * 128; i += stride) {
        int n = i / 128, k = i % 128;
        g_Whead[i] = (n < 18) ? Wa[n * 128 + k] : Wc[k];
    }
    if (t < NOUT) g_bhead[t] = (t < 18) ? ba[t] : bc[0];
}

// ================= TF32 tensor-core GEMM =================
// C[M,N] = act(A[M,K] @ W[N,K]^T + bias), M = gridDim.x*128, BK = 32.
// Smem holds fragments pre-swizzled in mma.sync m16n8k8 register order:
//   A tile  As[BM/16][BK/8][lane][reg]  (one LDS.128 per A fragment)
//   B tile  Bs[BN/8][BK/16][lane][reg]  (one LDS.64  per B fragment)
// Fragment maps (PTX ISA m16n8k8 .row.col, tf32):
//   A(r,c):  lane=(r%8)*4+(c%4), reg=(r/8)+2*(c/4)      r<16, c<8
//   B(k,n):  lane=(n%8)*4+(k%4), reg per k16-block: (k8)*2+(k%8)/4
template<int BN, int WARPS_M, int WARPS_N, bool RELU>
__global__ void __launch_bounds__(32 * WARPS_M * WARPS_N)
tf32_gemm(const float* __restrict__ A, const float* __restrict__ W,
          const float* __restrict__ bias, float* __restrict__ C, int K) {
    constexpr int BM = 128;
    constexpr int BK = 32;
    constexpr int THREADS = 32 * WARPS_M * WARPS_N;
    constexpr int MT = (BM / WARPS_M) / 16;   // m16 tiles per warp
    constexpr int NT = (BN / WARPS_N) / 8;    // n8 tiles per warp

    __shared__ unsigned As[BM / 16][BK / 8][32][4];
    __shared__ unsigned Bs[BN / 8][BK / 16][32][4];

    const int tid  = threadIdx.x;
    const int lane = tid & 31;
    const int w    = tid >> 5;
    const int wm   = w / WARPS_N;
    const int wn   = w % WARPS_N;
    const int bm   = blockIdx.x * BM;
    const int bn   = blockIdx.y * BN;
    const int g    = lane >> 2;       // groupID
    const int tig  = lane & 3;        // thread in group

    float acc[MT][NT][4];
#pragma unroll
    for (int i = 0; i < MT; i++)
#pragma unroll
        for (int j = 0; j < NT; j++)
#pragma unroll
            for (int r = 0; r < 4; r++) acc[i][j][r] = 0.f;

    for (int k0 = 0; k0 < K; k0 += BK) {
        // ---- fill A (BM x BK), scatter into fragment order ----
        constexpr int AV4 = BM * BK / 4;            // float4 count
#pragma unroll
        for (int it = 0; it < AV4 / THREADS; it++) {
            int idx = tid + it * THREADS;
            int row = idx >> 3;                      // BK/4 = 8
            int c4  = idx & 7;
            float4 v = *(const float4*)(A + (size_t)(bm + row) * K + k0 + c4 * 4);
            int mt = row >> 4, r = row & 15;
            float vv[4] = {v.x, v.y, v.z, v.w};
#pragma unroll
            for (int j = 0; j < 4; j++) {
                int col = c4 * 4 + j;
                int kt = col >> 3, c = col & 7;
                As[mt][kt][(r & 7) * 4 + (c & 3)][(r >> 3) + 2 * (c >> 2)] = tf32_of(vv[j]);
            }
        }
        // ---- fill B (BN x BK) from W[N,K] ----
        constexpr int BV4 = BN * BK / 4;
#pragma unroll
        for (int it = 0; it < (BV4 + THREADS - 1) / THREADS; it++) {
            int idx = tid + it * THREADS;
            if ((BV4 % THREADS == 0) || idx < BV4) {
                int n  = idx >> 3;
                int c4 = idx & 7;
                float4 v = *(const float4*)(W + (size_t)(bn + n) * K + k0 + c4 * 4);
                int nt = n >> 3, gg = n & 7;
                float vv[4] = {v.x, v.y, v.z, v.w};
#pragma unroll
                for (int j = 0; j < 4; j++) {
                    int k = c4 * 4 + j;
                    int kblk = k >> 4, kk = k & 15;
                    Bs[nt][kblk][gg * 4 + (kk & 3)][((kk >> 3) << 1) + ((kk & 7) >> 2)] = tf32_of(vv[j]);
                }
            }
        }
        __syncthreads();

        // ---- compute: 4 k8 steps ----
#pragma unroll
        for (int kt = 0; kt < 4; kt++) {
            unsigned a[MT][4];
#pragma unroll
            for (int mt = 0; mt < MT; mt++)
                *(uint4*)a[mt] = *(const uint4*)&As[wm * MT + mt][kt][lane][0];
            unsigned b[NT][2];
#pragma unroll
            for (int nt = 0; nt < NT; nt++)
                *(uint2*)b[nt] = *(const uint2*)&Bs[wn * NT + nt][kt >> 1][lane][(kt & 1) * 2];
#pragma unroll
            for (int mt = 0; mt < MT; mt++)
#pragma unroll
                for (int nt = 0; nt < NT; nt++)
                    mma_tf32(acc[mt][nt], a[mt], b[nt]);
        }
        __syncthreads();
    }

    // ---- epilogue ----
#pragma unroll
    for (int mt = 0; mt < MT; mt++) {
#pragma unroll
        for (int nt = 0; nt < NT; nt++) {
            int col = bn + wn * (NT * 8) + nt * 8 + 2 * tig;
            int row0 = bm + wm * (MT * 16) + mt * 16 + g;
            float b0 = bias[col], b1 = bias[col + 1];
            float v0 = acc[mt][nt][0] + b0, v1 = acc[mt][nt][1] + b1;
            float v2 = acc[mt][nt][2] + b0, v3 = acc[mt][nt][3] + b1;
            if (RELU) {
                v0 = fmaxf(v0, 0.f); v1 = fmaxf(v1, 0.f);
                v2 = fmaxf(v2, 0.f); v3 = fmaxf(v3, 0.f);
            }
            int N_total = gridDim.y * BN;
            *(float2*)(C + (size_t)row0 * N_total + col)       = make_float2(v0, v1);
            *(float2*)(C + (size_t)(row0 + 8) * N_total + col) = make_float2(v2, v3);
        }
    }
}

// ---------------- scalar f32x2 GEMM (heads only, N=19) ----------------
template<int BM, int BN, int BK, int TM, int TN, bool RELU, bool NGUARD>
__global__ void __launch_bounds__((BM / TM) * (BN / TN))
gemm_kernel(const float* __restrict__ A, const float* __restrict__ W,
            const float* __restrict__ bias, float* __restrict__ C,
            int N, int K, int ldc) {
    constexpr int THREADS = (BM / TM) * (BN / TN);
    constexpr int BNQ = BN / TN;
    __shared__ __align__(16) float As[BK][BM + 4];
    __shared__ __align__(16) float Ws[BK][BN + 4];

    const int tid = threadIdx.x;
    const int bm = blockIdx.x * BM;
    const int bn = blockIdx.y * BN;
    const int tx = tid % BNQ;
    const int ty = tid / BNQ;

    ull acc2[TM / 2][TN];
#pragma unroll
    for (int i = 0; i < TM / 2; i++)
#pragma unroll
        for (int j = 0; j < TN; j++) acc2[i][j] = 0ull;

    for (int k0 = 0; k0 < K; k0 += BK) {
        constexpr int AV = BM * BK / 4;
#pragma unroll
        for (int i = 0; i < AV / THREADS; i++) {
            int idx = tid + i * THREADS;
            int row = idx / (BK / 4);
            int c4 = idx % (BK / 4);
            float4 v = *(const float4*)(A + (size_t)(bm + row) * K + k0 + c4 * 4);
            As[c4 * 4 + 0][row] = v.x;
            As[c4 * 4 + 1][row] = v.y;
            As[c4 * 4 + 2][row] = v.z;
            As[c4 * 4 + 3][row] = v.w;
        }
        constexpr int WV = BN * BK / 4;
#pragma unroll
        for (int i = 0; i < (WV + THREADS - 1) / THREADS; i++) {
            int idx = tid + i * THREADS;
            if ((WV % THREADS == 0) || idx < WV) {
                int row = idx / (BK / 4);
                int c4 = idx % (BK / 4);
                float4 v;
                if (!NGUARD || (bn + row) < N)
                    v = *(const float4*)(W + (size_t)(bn + row) * K + k0 + c4 * 4);
                else
                    v = make_float4(0.f, 0.f, 0.f, 0.f);
                Ws[c4 * 4 + 0][row] = v.x;
                Ws[c4 * 4 + 1][row] = v.y;
                Ws[c4 * 4 + 2][row] = v.z;
                Ws[c4 * 4 + 3][row] = v.w;
            }
        }
        __syncthreads();
#pragma unroll
        for (int kk = 0; kk < BK; kk++) {
            ull a2[TM / 2];
#pragma unroll
            for (int i2 = 0; i2 < TM / 2; i2++)
                a2[i2] = *(const ull*)&As[kk][ty * TM + 2 * i2];
            float br[TN];
#pragma unroll
            for (int j = 0; j < TN; j++) br[j] = Ws[kk][tx * TN + j];
            ull b2[TN];
#pragma unroll
            for (int j = 0; j < TN; j++) b2[j] = pack2(br[j], br[j]);
#pragma unroll
            for (int i2 = 0; i2 < TM / 2; i2++)
#pragma unroll
                for (int j = 0; j < TN; j++)
                    acc2[i2][j] = ffma2(a2[i2], b2[j], acc2[i2][j]);
        }
        __syncthreads();
    }
#pragma unroll
    for (int j = 0; j < TN; j++) {
        int n = bn + tx * TN + j;
        if (NGUARD && n >= N) continue;
        float bv = bias[n];
#pragma unroll
        for (int i2 = 0; i2 < TM / 2; i2++) {
            float v0, v1;
            unpack2(acc2[i2][j], v0, v1);
            v0 += bv; v1 += bv;
            if (RELU) { v0 = fmaxf(v0, 0.f); v1 = fmaxf(v1, 0.f); }
            C[(size_t)(bm + ty * TM + 2 * i2 + 0) * ldc + n] = v0;
            C[(size_t)(bm + ty * TM + 2 * i2 + 1) * ldc + n] = v1;
        }
    }
}

// ---------------- persistent LSTM recurrence (f32x2 matvec) ----------------
__global__ void __launch_bounds__(512, 1)
lstm_kernel(const float* __restrict__ xg, const float* __restrict__ done,
            const float* __restrict__ h0, const float* __restrict__ c0,
            float* __restrict__ hs, const float* __restrict__ WT) {
    __shared__ __align__(16) float h_s[128][8];   // [k][b]
    __shared__ float gates_s[8][512];             // [b][n]

    const int t = threadIdx.x;
    const int b0 = blockIdx.x * 8;
    const int n = t;

    const int bp0 = t >> 7;
    const int bp1 = 4 + (t >> 7);
    const int jp = t & 127;

    float c_r0 = c0[(b0 + bp0) * 128 + jp];
    float c_r1 = c0[(b0 + bp1) * 128 + jp];
    h_s[jp][bp0] = h0[(b0 + bp0) * 128 + jp];
    h_s[jp][bp1] = h0[(b0 + bp1) * 128 + jp];
    __syncthreads();

    for (int step = 0; step < TT; ++step) {
        float m0 = 1.f - done[step * BB + b0 + bp0];
        float m1 = 1.f - done[step * BB + b0 + bp1];
        c_r0 *= m0;
        c_r1 *= m1;
        h_s[jp][bp0] *= m0;
        h_s[jp][bp1] *= m1;
        __syncthreads();

        float xr[8];
        const float* xgp = xg + (size_t)(step * BB + b0) * 512 + n;
#pragma unroll
        for (int b = 0; b < 8; b++) xr[b] = xgp[b * 512];

        ull acc2[4];
#pragma unroll
        for (int p = 0; p < 4; p++) acc2[p] = 0ull;
#pragma unroll 8
        for (int k = 0; k < 128; k++) {
            float w = WT[k * 512 + n];
            ull w2 = pack2(w, w);
            double2 hA = *(const double2*)&h_s[k][0];
            double2 hB = *(const double2*)&h_s[k][4];
            acc2[0] = ffma2(w2, d_as_u(hA.x), acc2[0]);
            acc2[1] = ffma2(w2, d_as_u(hA.y), acc2[1]);
            acc2[2] = ffma2(w2, d_as_u(hB.x), acc2[2]);
            acc2[3] = ffma2(w2, d_as_u(hB.y), acc2[3]);
        }
        float acc[8];
#pragma unroll
        for (int p = 0; p < 4; p++) unpack2(acc2[p], acc[2 * p], acc[2 * p + 1]);

        const bool use_sig = (n < 256) || (n >= 384);
#pragma unroll
        for (int b = 0; b < 8; b++) {
            float v = acc[b] + xr[b];
            gates_s[b][n] = use_sig ? sigmoid_f(v) : tanh_f(v);
        }
        __syncthreads();

        {
            float i0 = gates_s[bp0][jp];
            float f0 = gates_s[bp0][jp + 128];
            float g0 = gates_s[bp0][jp + 256];
            float o0 = gates_s[bp0][jp + 384];
            c_r0 = f0 * c_r0 + i0 * g0;
            float hh0 = o0 * tanh_f(c_r0);

            float i1 = gates_s[bp1][jp];
            float f1 = gates_s[bp1][jp + 128];
            float g1 = gates_s[bp1][jp + 256];
            float o1 = gates_s[bp1][jp + 384];
            c_r1 = f1 * c_r1 + i1 * g1;
            float hh1 = o1 * tanh_f(c_r1);

            h_s[jp][bp0] = hh0;
            h_s[jp][bp1] = hh1;
            hs[(size_t)(step * BB + b0 + bp0) * 128 + jp] = hh0;
            hs[(size_t)(step * BB + b0 + bp1) * 128 + jp] = hh1;
        }
        __syncthreads();
    }
}

// ---------------- launch ----------------
extern "C" void kernel_launch(void* const* d_in, const int* in_sizes, int n_in,
                              void* d_out, int out_size) {
    const float* x    = (const float*)d_in[0];
    const float* done = (const float*)d_in[1];
    const float* h0   = (const float*)d_in[2];
    const float* c0   = (const float*)d_in[3];
    const float* W1   = (const float*)d_in[4];
    const float* b1   = (const float*)d_in[5];
    const float* W2   = (const float*)d_in[6];
    const float* b2   = (const float*)d_in[7];
    const float* W3   = (const float*)d_in[8];
    const float* b3   = (const float*)d_in[9];
    const float* Wih  = (const float*)d_in[10];
    const float* Whh  = (const float*)d_in[11];
    const float* bih  = (const float*)d_in[12];
    const float* bhh  = (const float*)d_in[13];
    const float* Wa   = (const float*)d_in[14];
    const float* ba   = (const float*)d_in[15];
    const float* Wc   = (const float*)d_in[16];
    const float* bc   = (const float*)d_in[17];
    float* out = (float*)d_out;

    float *h1, *h2, *h3, *xgp, *hsp, *whhT, *bg, *whd, *bhd;
    cudaGetSymbolAddress((void**)&h1,   g_h1);
    cudaGetSymbolAddress((void**)&h2,   g_h2);
    cudaGetSymbolAddress((void**)&h3,   g_h3);
    cudaGetSymbolAddress((void**)&xgp,  g_xg);
    cudaGetSymbolAddress((void**)&hsp,  g_hs);
    cudaGetSymbolAddress((void**)&whhT, g_WhhT);
    cudaGetSymbolAddress((void**)&bg,   g_bg);
    cudaGetSymbolAddress((void**)&whd,  g_Whead);
    cudaGetSymbolAddress((void**)&bhd,  g_bhead);

    prepack_kernel<<<128, 256>>>(Whh, bih, bhh, Wa, ba, Wc, bc);

    // MLP encoder (tf32 tensor cores)
    tf32_gemm<128, 4, 2, true><<<dim3(TB / 128, 1), 256>>>(x,  W1, b1, h1, 128);
    tf32_gemm< 32, 8, 1, true><<<dim3(TB / 128, 1), 256>>>(h1, W2, b2, h2, 128);
    tf32_gemm<128, 4, 2, true><<<dim3(TB / 128, 1), 256>>>(h2, W3, b3, h3, 32);

    // xg = h3 @ Wih^T + (bih+bhh)   (N=512 via grid.y=4)
    tf32_gemm<128, 4, 2, false><<<dim3(TB / 128, 4), 256>>>(h3, Wih, bg, xgp, 128);

    // Sequential LSTM (fp32)
    lstm_kernel<<<128, 512>>>(xgp, done, h0, c0, hsp, whhT);

    // Heads (fp32 scalar, N=19)
    gemm_kernel<128, 32, 32, 8, 2, false, true>
        <<<dim3(TB / 128, 1), 256>>>(hsp, whd, bhd, out, NOUT, 128, NOUT);
}

// round 8
// speedup vs baseline: 1.4824x; 1.0803x over previous
#include <cuda_runtime.h>
#include <math.h>

// Problem dims
#define TB   262144   // T*B = 256*1024
#define TT   256
#define BB   1024
#define NOUT 19
#define GSM  384      // gate rows of Whh resident in shared memory (warp-aligned)

// ---------------- scratch (static device memory; no allocs) ----------------
__device__ float g_h1[TB * 128];
__device__ float g_h2[TB * 32];
__device__ float g_h3[TB * 128];
__device__ float g_xg[TB * 512];
__device__ float g_hs[TB * 128];
__device__ float g_WhhT[128 * 512];     // [k][n]
__device__ float g_bg[512];
__device__ float g_Whead[NOUT * 128];
__device__ float g_bhead[NOUT];

// ---------------- packed f32x2 helpers ----------------
typedef unsigned long long ull;
__device__ __forceinline__ ull pack2(float lo, float hi) {
    ull r; asm("mov.b64 %0, {%1, %2};" : "=l"(r) : "f"(lo), "f"(hi)); return r;
}
__device__ __forceinline__ void unpack2(ull p, float& lo, float& hi) {
    asm("mov.b64 {%0, %1}, %2;" : "=f"(lo), "=f"(hi) : "l"(p));
}
__device__ __forceinline__ ull ffma2(ull a, ull b, ull c) {
    ull d; asm("fma.rn.f32x2 %0, %1, %2, %3;" : "=l"(d) : "l"(a), "l"(b), "l"(c));
    return d;
}
__device__ __forceinline__ ull d_as_u(double d) { return __double_as_longlong(d); }

// ---------------- tf32 helpers ----------------
__device__ __forceinline__ unsigned tf32_of(float f) {
    unsigned r; asm("cvt.rna.tf32.f32 %0, %1;" : "=r"(r) : "f"(f)); return r;
}
__device__ __forceinline__ void mma_tf32(float* d, const unsigned* a, const unsigned* b) {
    asm volatile(
        "mma.sync.aligned.m16n8k8.row.col.f32.tf32.tf32.f32 "
        "{%0,%1,%2,%3}, {%4,%5,%6,%7}, {%8,%9}, {%0,%1,%2,%3};"
        : "+f"(d[0]), "+f"(d[1]), "+f"(d[2]), "+f"(d[3])
        : "r"(a[0]), "r"(a[1]), "r"(a[2]), "r"(a[3]), "r"(b[0]), "r"(b[1]));
}

// ---------------- fast activations ----------------
__device__ __forceinline__ float sigmoid_f(float x) {
    return __fdividef(1.f, 1.f + __expf(-x));
}
__device__ __forceinline__ float tanh_f(float x) {
    float e = __expf(-2.f * fabsf(x));
    float r = __fdividef(1.f - e, 1.f + e);
    return copysignf(r, x);
}

// ---------------- prepack ----------------
__global__ void prepack_kernel(const float* __restrict__ Whh,
                               const float* __restrict__ bih,
                               const float* __restrict__ bhh,
                               const float* __restrict__ Wa,
                               const float* __restrict__ ba,
                               const float* __restrict__ Wc,
                               const float* __restrict__ bc) {
    int t = blockIdx.x * blockDim.x + threadIdx.x;
    int stride = gridDim.x * blockDim.x;
    for (int i = t; i < 128 * 512; i += stride) {
        int k = i / 512, n = i % 512;
        g_WhhT[i] = Whh[n * 128 + k];
    }
    if (t < 512) g_bg[t] = bih[t] + bhh[t];
    for (int i = t; i < NOUT * 128; i += stride) {
        int n = i / 128, k = i % 128;
        g_Whead[i] = (n < 18) ? Wa[n * 128 + k] : Wc[k];
    }
    if (t < NOUT) g_bhead[t] = (t < 18) ? ba[t] : bc[0];
}

// ================= TF32 tensor-core GEMM =================
template<int BN, int WARPS_M, int WARPS_N, bool RELU>
__global__ void __launch_bounds__(32 * WARPS_M * WARPS_N)
tf32_gemm(const float* __restrict__ A, const float* __restrict__ W,
          const float* __restrict__ bias, float* __restrict__ C, int K) {
    constexpr int BM = 128;
    constexpr int BK = 32;
    constexpr int THREADS = 32 * WARPS_M * WARPS_N;
    constexpr int MT = (BM / WARPS_M) / 16;
    constexpr int NT = (BN / WARPS_N) / 8;

    __shared__ unsigned As[BM / 16][BK / 8][32][4];
    __shared__ unsigned Bs[BN / 8][BK / 16][32][4];

    const int tid  = threadIdx.x;
    const int lane = tid & 31;
    const int w    = tid >> 5;
    const int wm   = w / WARPS_N;
    const int wn   = w % WARPS_N;
    const int bm   = blockIdx.x * BM;
    const int bn   = blockIdx.y * BN;
    const int g    = lane >> 2;
    const int tig  = lane & 3;

    float acc[MT][NT][4];
#pragma unroll
    for (int i = 0; i < MT; i++)
#pragma unroll
        for (int j = 0; j < NT; j++)
#pragma unroll
            for (int r = 0; r < 4; r++) acc[i][j][r] = 0.f;

    for (int k0 = 0; k0 < K; k0 += BK) {
        constexpr int AV4 = BM * BK / 4;
#pragma unroll
        for (int it = 0; it < AV4 / THREADS; it++) {
            int idx = tid + it * THREADS;
            int row = idx >> 3;
            int c4  = idx & 7;
            float4 v = *(const float4*)(A + (size_t)(bm + row) * K + k0 + c4 * 4);
            int mt = row >> 4, r = row & 15;
            float vv[4] = {v.x, v.y, v.z, v.w};
#pragma unroll
            for (int j = 0; j < 4; j++) {
                int col = c4 * 4 + j;
                int kt = col >> 3, c = col & 7;
                As[mt][kt][(r & 7) * 4 + (c & 3)][(r >> 3) + 2 * (c >> 2)] = tf32_of(vv[j]);
            }
        }
        constexpr int BV4 = BN * BK / 4;
#pragma unroll
        for (int it = 0; it < (BV4 + THREADS - 1) / THREADS; it++) {
            int idx = tid + it * THREADS;
            if ((BV4 % THREADS == 0) || idx < BV4) {
                int n  = idx >> 3;
                int c4 = idx & 7;
                float4 v = *(const float4*)(W + (size_t)(bn + n) * K + k0 + c4 * 4);
                int nt = n >> 3, gg = n & 7;
                float vv[4] = {v.x, v.y, v.z, v.w};
#pragma unroll
                for (int j = 0; j < 4; j++) {
                    int k = c4 * 4 + j;
                    int kblk = k >> 4, kk = k & 15;
                    Bs[nt][kblk][gg * 4 + (kk & 3)][((kk >> 3) << 1) + ((kk & 7) >> 2)] = tf32_of(vv[j]);
                }
            }
        }
        __syncthreads();

#pragma unroll
        for (int kt = 0; kt < 4; kt++) {
            unsigned a[MT][4];
#pragma unroll
            for (int mt = 0; mt < MT; mt++)
                *(uint4*)a[mt] = *(const uint4*)&As[wm * MT + mt][kt][lane][0];
            unsigned b[NT][2];
#pragma unroll
            for (int nt = 0; nt < NT; nt++)
                *(uint2*)b[nt] = *(const uint2*)&Bs[wn * NT + nt][kt >> 1][lane][(kt & 1) * 2];
#pragma unroll
            for (int mt = 0; mt < MT; mt++)
#pragma unroll
                for (int nt = 0; nt < NT; nt++)
                    mma_tf32(acc[mt][nt], a[mt], b[nt]);
        }
        __syncthreads();
    }

#pragma unroll
    for (int mt = 0; mt < MT; mt++) {
#pragma unroll
        for (int nt = 0; nt < NT; nt++) {
            int col = bn + wn * (NT * 8) + nt * 8 + 2 * tig;
            int row0 = bm + wm * (MT * 16) + mt * 16 + g;
            float b0 = bias[col], b1 = bias[col + 1];
            float v0 = acc[mt][nt][0] + b0, v1 = acc[mt][nt][1] + b1;
            float v2 = acc[mt][nt][2] + b0, v3 = acc[mt][nt][3] + b1;
            if (RELU) {
                v0 = fmaxf(v0, 0.f); v1 = fmaxf(v1, 0.f);
                v2 = fmaxf(v2, 0.f); v3 = fmaxf(v3, 0.f);
            }
            int N_total = gridDim.y * BN;
            *(float2*)(C + (size_t)row0 * N_total + col)       = make_float2(v0, v1);
            *(float2*)(C + (size_t)(row0 + 8) * N_total + col) = make_float2(v2, v3);
        }
    }
}

// ---------------- scalar f32x2 GEMM (heads only, N=19) ----------------
template<int BM, int BN, int BK, int TM, int TN, bool RELU, bool NGUARD>
__global__ void __launch_bounds__((BM / TM) * (BN / TN))
gemm_kernel(const float* __restrict__ A, const float* __restrict__ W,
            const float* __restrict__ bias, float* __restrict__ C,
            int N, int K, int ldc) {
    constexpr int THREADS = (BM / TM) * (BN / TN);
    constexpr int BNQ = BN / TN;
    __shared__ __align__(16) float As[BK][BM + 4];
    __shared__ __align__(16) float Ws[BK][BN + 4];

    const int tid = threadIdx.x;
    const int bm = blockIdx.x * BM;
    const int bn = blockIdx.y * BN;
    const int tx = tid % BNQ;
    const int ty = tid / BNQ;

    ull acc2[TM / 2][TN];
#pragma unroll
    for (int i = 0; i < TM / 2; i++)
#pragma unroll
        for (int j = 0; j < TN; j++) acc2[i][j] = 0ull;

    for (int k0 = 0; k0 < K; k0 += BK) {
        constexpr int AV = BM * BK / 4;
#pragma unroll
        for (int i = 0; i < AV / THREADS; i++) {
            int idx = tid + i * THREADS;
            int row = idx / (BK / 4);
            int c4 = idx % (BK / 4);
            float4 v = *(const float4*)(A + (size_t)(bm + row) * K + k0 + c4 * 4);
            As[c4 * 4 + 0][row] = v.x;
            As[c4 * 4 + 1][row] = v.y;
            As[c4 * 4 + 2][row] = v.z;
            As[c4 * 4 + 3][row] = v.w;
        }
        constexpr int WV = BN * BK / 4;
#pragma unroll
        for (int i = 0; i < (WV + THREADS - 1) / THREADS; i++) {
            int idx = tid + i * THREADS;
            if ((WV % THREADS == 0) || idx < WV) {
                int row = idx / (BK / 4);
                int c4 = idx % (BK / 4);
                float4 v;
                if (!NGUARD || (bn + row) < N)
                    v = *(const float4*)(W + (size_t)(bn + row) * K + k0 + c4 * 4);
                else
                    v = make_float4(0.f, 0.f, 0.f, 0.f);
                Ws[c4 * 4 + 0][row] = v.x;
                Ws[c4 * 4 + 1][row] = v.y;
                Ws[c4 * 4 + 2][row] = v.z;
                Ws[c4 * 4 + 3][row] = v.w;
            }
        }
        __syncthreads();
#pragma unroll
        for (int kk = 0; kk < BK; kk++) {
            ull a2[TM / 2];
#pragma unroll
            for (int i2 = 0; i2 < TM / 2; i2++)
                a2[i2] = *(const ull*)&As[kk][ty * TM + 2 * i2];
            float br[TN];
#pragma unroll
            for (int j = 0; j < TN; j++) br[j] = Ws[kk][tx * TN + j];
            ull b2[TN];
#pragma unroll
            for (int j = 0; j < TN; j++) b2[j] = pack2(br[j], br[j]);
#pragma unroll
            for (int i2 = 0; i2 < TM / 2; i2++)
#pragma unroll
                for (int j = 0; j < TN; j++)
                    acc2[i2][j] = ffma2(a2[i2], b2[j], acc2[i2][j]);
        }
        __syncthreads();
    }
#pragma unroll
    for (int j = 0; j < TN; j++) {
        int n = bn + tx * TN + j;
        if (NGUARD && n >= N) continue;
        float bv = bias[n];
#pragma unroll
        for (int i2 = 0; i2 < TM / 2; i2++) {
            float v0, v1;
            unpack2(acc2[i2][j], v0, v1);
            v0 += bv; v1 += bv;
            if (RELU) { v0 = fmaxf(v0, 0.f); v1 = fmaxf(v1, 0.f); }
            C[(size_t)(bm + ty * TM + 2 * i2 + 0) * ldc + n] = v0;
            C[(size_t)(bm + ty * TM + 2 * i2 + 1) * ldc + n] = v1;
        }
    }
}

// ---------------- persistent LSTM (smem-resident Whh + f32x2) ----------------
// 128 CTAs x 512 threads; CTA owns 8 batch rows for all 256 steps.
// Gates 0..GSM-1: Whh rows live in shared memory (loaded once).
// Gates GSM..511 (warps 12-15): Whh streamed from L2 with 2x32 register
// double-buffering so load latency hides behind FMA work.
#define LSTM_SMEM_BYTES ((128 * GSM + 128 * 8 + 8 * 512) * 4)

#define LSTM_COMP32(WV, KB)                                          \
    {                                                                \
        _Pragma("unroll")                                            \
        for (int j = 0; j < 32; j++) {                               \
            ull w2 = pack2(WV[j], WV[j]);                            \
            double2 hA = *(const double2*)&h_s[((KB) + j) * 8];      \
            double2 hB = *(const double2*)&h_s[((KB) + j) * 8 + 4];  \
            acc2[0] = ffma2(w2, d_as_u(hA.x), acc2[0]);              \
            acc2[1] = ffma2(w2, d_as_u(hA.y), acc2[1]);              \
            acc2[2] = ffma2(w2, d_as_u(hB.x), acc2[2]);              \
            acc2[3] = ffma2(w2, d_as_u(hB.y), acc2[3]);              \
        }                                                            \
    }

#define LSTM_LOAD32(WV, KB)                                          \
    {                                                                \
        _Pragma("unroll")                                            \
        for (int j = 0; j < 32; j++) WV[j] = wp[((KB) + j) * 512];   \
    }

__global__ void __launch_bounds__(512, 1)
lstm_kernel(const float* __restrict__ xg, const float* __restrict__ done,
            const float* __restrict__ h0, const float* __restrict__ c0,
            float* __restrict__ hs, const float* __restrict__ WT) {
    extern __shared__ float sm[];
    float* Wsm     = sm;                         // [128][GSM]
    float* h_s     = sm + 128 * GSM;             // [128][8]
    float* gates_s = h_s + 128 * 8;              // [8][512]

    const int t = threadIdx.x;
    const int b0 = blockIdx.x * 8;
    const int n = t;

    // Load resident weight slab (coalesced)
    for (int i = t; i < 128 * GSM; i += 512)
        Wsm[i] = WT[(i / GSM) * 512 + (i % GSM)];

    const int bp0 = t >> 7;
    const int bp1 = 4 + bp0;
    const int jp = t & 127;

    float c_r0 = c0[(b0 + bp0) * 128 + jp];
    float c_r1 = c0[(b0 + bp1) * 128 + jp];
    h_s[jp * 8 + bp0] = h0[(b0 + bp0) * 128 + jp];
    h_s[jp * 8 + bp1] = h0[(b0 + bp1) * 128 + jp];
    __syncthreads();

    for (int step = 0; step < TT; ++step) {
        float m0 = 1.f - done[step * BB + b0 + bp0];
        float m1 = 1.f - done[step * BB + b0 + bp1];
        c_r0 *= m0;
        c_r1 *= m1;
        h_s[jp * 8 + bp0] *= m0;
        h_s[jp * 8 + bp1] *= m1;
        __syncthreads();

        // prefetch x-gates for this thread's 8 batch rows
        float xr[8];
        const float* xgp = xg + (size_t)(step * BB + b0) * 512 + n;
#pragma unroll
        for (int b = 0; b < 8; b++) xr[b] = xgp[b * 512];

        ull acc2[4];
#pragma unroll
        for (int p = 0; p < 4; p++) acc2[p] = 0ull;

        if (n < GSM) {
            // Whh row from shared memory (conflict-free: consecutive n)
#pragma unroll 8
            for (int k = 0; k < 128; k++) {
                float w = Wsm[k * GSM + n];
                ull w2 = pack2(w, w);
                double2 hA = *(const double2*)&h_s[k * 8];
                double2 hB = *(const double2*)&h_s[k * 8 + 4];
                acc2[0] = ffma2(w2, d_as_u(hA.x), acc2[0]);
                acc2[1] = ffma2(w2, d_as_u(hA.y), acc2[1]);
                acc2[2] = ffma2(w2, d_as_u(hB.x), acc2[2]);
                acc2[3] = ffma2(w2, d_as_u(hB.y), acc2[3]);
            }
        } else {
            // Whh row streamed from L2, 2x32 register double-buffer
            const float* wp = WT + n;
            float wv0[32], wv1[32];
            LSTM_LOAD32(wv0, 0)
            LSTM_LOAD32(wv1, 32)
            LSTM_COMP32(wv0, 0)
            LSTM_LOAD32(wv0, 64)
            LSTM_COMP32(wv1, 32)
            LSTM_LOAD32(wv1, 96)
            LSTM_COMP32(wv0, 64)
            LSTM_COMP32(wv1, 96)
        }

        float acc[8];
#pragma unroll
        for (int p = 0; p < 4; p++) unpack2(acc2[p], acc[2 * p], acc[2 * p + 1]);

        // activation (gate order [i,f,g,o]; g (256..383) uses tanh) — uniform per warp
        const bool use_sig = (n < 256) || (n >= 384);
#pragma unroll
        for (int b = 0; b < 8; b++) {
            float v = acc[b] + xr[b];
            gates_s[b * 512 + n] = use_sig ? sigmoid_f(v) : tanh_f(v);
        }
        __syncthreads();

        // cell update: 1024 (b,j) pairs, 2 per thread
        {
            float i0 = gates_s[bp0 * 512 + jp];
            float f0 = gates_s[bp0 * 512 + jp + 128];
            float g0 = gates_s[bp0 * 512 + jp + 256];
            float o0 = gates_s[bp0 * 512 + jp + 384];
            c_r0 = f0 * c_r0 + i0 * g0;
            float hh0 = o0 * tanh_f(c_r0);

            float i1 = gates_s[bp1 * 512 + jp];
            float f1 = gates_s[bp1 * 512 + jp + 128];
            float g1 = gates_s[bp1 * 512 + jp + 256];
            float o1 = gates_s[bp1 * 512 + jp + 384];
            c_r1 = f1 * c_r1 + i1 * g1;
            float hh1 = o1 * tanh_f(c_r1);

            h_s[jp * 8 + bp0] = hh0;
            h_s[jp * 8 + bp1] = hh1;
            hs[(size_t)(step * BB + b0 + bp0) * 128 + jp] = hh0;
            hs[(size_t)(step * BB + b0 + bp1) * 128 + jp] = hh1;
        }
        __syncthreads();
    }
}

// ---------------- launch ----------------
extern "C" void kernel_launch(void* const* d_in, const int* in_sizes, int n_in,
                              void* d_out, int out_size) {
    const float* x    = (const float*)d_in[0];
    const float* done = (const float*)d_in[1];
    const float* h0   = (const float*)d_in[2];
    const float* c0   = (const float*)d_in[3];
    const float* W1   = (const float*)d_in[4];
    const float* b1   = (const float*)d_in[5];
    const float* W2   = (const float*)d_in[6];
    const float* b2   = (const float*)d_in[7];
    const float* W3   = (const float*)d_in[8];
    const float* b3   = (const float*)d_in[9];
    const float* Wih  = (const float*)d_in[10];
    const float* Whh  = (const float*)d_in[11];
    const float* bih  = (const float*)d_in[12];
    const float* bhh  = (const float*)d_in[13];
    const float* Wa   = (const float*)d_in[14];
    const float* ba   = (const float*)d_in[15];
    const float* Wc   = (const float*)d_in[16];
    const float* bc   = (const float*)d_in[17];
    float* out = (float*)d_out;

    float *h1, *h2, *h3, *xgp, *hsp, *whhT, *bg, *whd, *bhd;
    cudaGetSymbolAddress((void**)&h1,   g_h1);
    cudaGetSymbolAddress((void**)&h2,   g_h2);
    cudaGetSymbolAddress((void**)&h3,   g_h3);
    cudaGetSymbolAddress((void**)&xgp,  g_xg);
    cudaGetSymbolAddress((void**)&hsp,  g_hs);
    cudaGetSymbolAddress((void**)&whhT, g_WhhT);
    cudaGetSymbolAddress((void**)&bg,   g_bg);
    cudaGetSymbolAddress((void**)&whd,  g_Whead);
    cudaGetSymbolAddress((void**)&bhd,  g_bhead);

    static int smem_set = 0;
    if (!smem_set) {
        cudaFuncSetAttribute(lstm_kernel,
                             cudaFuncAttributeMaxDynamicSharedMemorySize,
                             LSTM_SMEM_BYTES);
        smem_set = 1;
    }

    prepack_kernel<<<128, 256>>>(Whh, bih, bhh, Wa, ba, Wc, bc);

    // MLP encoder (tf32 tensor cores)
    tf32_gemm<128, 4, 2, true><<<dim3(TB / 128, 1), 256>>>(x,  W1, b1, h1, 128);
    tf32_gemm< 32, 8, 1, true><<<dim3(TB / 128, 1), 256>>>(h1, W2, b2, h2, 128);
    tf32_gemm<128, 4, 2, true><<<dim3(TB / 128, 1), 256>>>(h2, W3, b3, h3, 32);

    // xg = h3 @ Wih^T + (bih+bhh)  (N=512 via grid.y=2, BN=256: halves A re-reads)
    tf32_gemm<256, 2, 4, false><<<dim3(TB / 128, 2), 256>>>(h3, Wih, bg, xgp, 128);

    // Sequential LSTM (fp32, Whh smem-resident)
    lstm_kernel<<<128, 512, LSTM_SMEM_BYTES>>>(xgp, done, h0, c0, hsp, whhT);

    // Heads (fp32 scalar, N=19)
    gemm_kernel<128, 32, 32, 8, 2, false, true>
        <<<dim3(TB / 128, 1), 256>>>(hsp, whd, bhd, out, NOUT, 128, NOUT);
}

// round 9
// speedup vs baseline: 2.3324x; 1.5734x over previous
#include <cuda_runtime.h>
#include <math.h>

// Problem dims
#define TB   262144   // T*B = 256*1024
#define TT   256
#define BB   1024
#define NOUT 19
#define SM_TILES 26   // A-fragment m-tiles resident in smem (of 32)

// ---------------- scratch (static device memory; no allocs) ----------------
__device__ float g_h1[TB * 128];
__device__ float g_h2[TB * 32];
__device__ float g_h3[TB * 128];
__device__ float g_xg[TB * 512];
__device__ float g_hs[TB * 128];
__device__ float g_WhhFrag[32 * 16 * 32 * 4];  // [mtile][kstep][lane][reg], tf32
__device__ float g_bg[512];
__device__ float g_Whead[NOUT * 128];
__device__ float g_bhead[NOUT];

// ---------------- packed f32x2 helpers ----------------
typedef unsigned long long ull;
__device__ __forceinline__ ull pack2(float lo, float hi) {
    ull r; asm("mov.b64 %0, {%1, %2};" : "=l"(r) : "f"(lo), "f"(hi)); return r;
}
__device__ __forceinline__ void unpack2(ull p, float& lo, float& hi) {
    asm("mov.b64 {%0, %1}, %2;" : "=f"(lo), "=f"(hi) : "l"(p));
}
__device__ __forceinline__ ull ffma2(ull a, ull b, ull c) {
    ull d; asm("fma.rn.f32x2 %0, %1, %2, %3;" : "=l"(d) : "l"(a), "l"(b), "l"(c));
    return d;
}

// ---------------- tf32 helpers ----------------
__device__ __forceinline__ unsigned tf32_of(float f) {
    unsigned r; asm("cvt.rna.tf32.f32 %0, %1;" : "=r"(r) : "f"(f)); return r;
}
__device__ __forceinline__ void mma_tf32(float* d, const unsigned* a, const unsigned* b) {
    asm volatile(
        "mma.sync.aligned.m16n8k8.row.col.f32.tf32.tf32.f32 "
        "{%0,%1,%2,%3}, {%4,%5,%6,%7}, {%8,%9}, {%0,%1,%2,%3};"
        : "+f"(d[0]), "+f"(d[1]), "+f"(d[2]), "+f"(d[3])
        : "r"(a[0]), "r"(a[1]), "r"(a[2]), "r"(a[3]), "r"(b[0]), "r"(b[1]));
}

// ---------------- fast activations ----------------
__device__ __forceinline__ float sigmoid_f(float x) {
    return __fdividef(1.f, 1.f + __expf(-x));
}
__device__ __forceinline__ float tanh_f(float x) {
    float e = __expf(-2.f * fabsf(x));
    float r = __fdividef(1.f - e, 1.f + e);
    return copysignf(r, x);
}

// ---------------- prepack ----------------
// g_WhhFrag[mt][ks][lane][r]: exact mma.m16n8k8 A-fragment order (row-major A):
//   g = lane>>2, t = lane&3
//   r0=(g,t)  r1=(g+8,t)  r2=(g,t+4)  r3=(g+8,t+4)   rows = gates, cols = k
__global__ void prepack_kernel(const float* __restrict__ Whh,
                               const float* __restrict__ bih,
                               const float* __restrict__ bhh,
                               const float* __restrict__ Wa,
                               const float* __restrict__ ba,
                               const float* __restrict__ Wc,
                               const float* __restrict__ bc) {
    int t = blockIdx.x * blockDim.x + threadIdx.x;
    int stride = gridDim.x * blockDim.x;
    for (int i = t; i < 32 * 16 * 32 * 4; i += stride) {
        int r    = i & 3;
        int lane = (i >> 2) & 31;
        int ks   = (i >> 7) & 15;
        int mt   = i >> 11;
        int gg = lane >> 2, tg = lane & 3;
        int row = mt * 16 + gg + ((r & 1) ? 8 : 0);
        int col = ks * 8 + tg + ((r & 2) ? 4 : 0);
        g_WhhFrag[i] = __uint_as_float(tf32_of(Whh[row * 128 + col]));
    }
    if (t < 512) g_bg[t] = bih[t] + bhh[t];
    for (int i = t; i < NOUT * 128; i += stride) {
        int n = i / 128, k = i % 128;
        g_Whead[i] = (n < 18) ? Wa[n * 128 + k] : Wc[k];
    }
    if (t < NOUT) g_bhead[t] = (t < 18) ? ba[t] : bc[0];
}

// ================= TF32 tensor-core GEMM (feedforward) =================
template<int BN, int WARPS_M, int WARPS_N, bool RELU>
__global__ void __launch_bounds__(32 * WARPS_M * WARPS_N)
tf32_gemm(const float* __restrict__ A, const float* __restrict__ W,
          const float* __restrict__ bias, float* __restrict__ C, int K) {
    constexpr int BM = 128;
    constexpr int BK = 32;
    constexpr int THREADS = 32 * WARPS_M * WARPS_N;
    constexpr int MT = (BM / WARPS_M) / 16;
    constexpr int NT = (BN / WARPS_N) / 8;

    __shared__ unsigned As[BM / 16][BK / 8][32][4];
    __shared__ unsigned Bs[BN / 8][BK / 16][32][4];

    const int tid  = threadIdx.x;
    const int lane = tid & 31;
    const int w    = tid >> 5;
    const int wm   = w / WARPS_N;
    const int wn   = w % WARPS_N;
    const int bm   = blockIdx.x * BM;
    const int bn   = blockIdx.y * BN;
    const int g    = lane >> 2;
    const int tig  = lane & 3;

    float acc[MT][NT][4];
#pragma unroll
    for (int i = 0; i < MT; i++)
#pragma unroll
        for (int j = 0; j < NT; j++)
#pragma unroll
            for (int r = 0; r < 4; r++) acc[i][j][r] = 0.f;

    for (int k0 = 0; k0 < K; k0 += BK) {
        constexpr int AV4 = BM * BK / 4;
#pragma unroll
        for (int it = 0; it < AV4 / THREADS; it++) {
            int idx = tid + it * THREADS;
            int row = idx >> 3;
            int c4  = idx & 7;
            float4 v = *(const float4*)(A + (size_t)(bm + row) * K + k0 + c4 * 4);
            int mt = row >> 4, r = row & 15;
            float vv[4] = {v.x, v.y, v.z, v.w};
#pragma unroll
            for (int j = 0; j < 4; j++) {
                int col = c4 * 4 + j;
                int kt = col >> 3, c = col & 7;
                As[mt][kt][(r & 7) * 4 + (c & 3)][(r >> 3) + 2 * (c >> 2)] = tf32_of(vv[j]);
            }
        }
        constexpr int BV4 = BN * BK / 4;
#pragma unroll
        for (int it = 0; it < (BV4 + THREADS - 1) / THREADS; it++) {
            int idx = tid + it * THREADS;
            if ((BV4 % THREADS == 0) || idx < BV4) {
                int n  = idx >> 3;
                int c4 = idx & 7;
                float4 v = *(const float4*)(W + (size_t)(bn + n) * K + k0 + c4 * 4);
                int nt = n >> 3, gg = n & 7;
                float vv[4] = {v.x, v.y, v.z, v.w};
#pragma unroll
                for (int j = 0; j < 4; j++) {
                    int k = c4 * 4 + j;
                    int kblk = k >> 4, kk = k & 15;
                    Bs[nt][kblk][gg * 4 + (kk & 3)][((kk >> 3) << 1) + ((kk & 7) >> 2)] = tf32_of(vv[j]);
                }
            }
        }
        __syncthreads();

#pragma unroll
        for (int kt = 0; kt < 4; kt++) {
            unsigned a[MT][4];
#pragma unroll
            for (int mt = 0; mt < MT; mt++)
                *(uint4*)a[mt] = *(const uint4*)&As[wm * MT + mt][kt][lane][0];
            unsigned b[NT][2];
#pragma unroll
            for (int nt = 0; nt < NT; nt++)
                *(uint2*)b[nt] = *(const uint2*)&Bs[wn * NT + nt][kt >> 1][lane][(kt & 1) * 2];
#pragma unroll
            for (int mt = 0; mt < MT; mt++)
#pragma unroll
                for (int nt = 0; nt < NT; nt++)
                    mma_tf32(acc[mt][nt], a[mt], b[nt]);
        }
        __syncthreads();
    }

#pragma unroll
    for (int mt = 0; mt < MT; mt++) {
#pragma unroll
        for (int nt = 0; nt < NT; nt++) {
            int col = bn + wn * (NT * 8) + nt * 8 + 2 * tig;
            int row0 = bm + wm * (MT * 16) + mt * 16 + g;
            float b0 = bias[col], b1 = bias[col + 1];
            float v0 = acc[mt][nt][0] + b0, v1 = acc[mt][nt][1] + b1;
            float v2 = acc[mt][nt][2] + b0, v3 = acc[mt][nt][3] + b1;
            if (RELU) {
                v0 = fmaxf(v0, 0.f); v1 = fmaxf(v1, 0.f);
                v2 = fmaxf(v2, 0.f); v3 = fmaxf(v3, 0.f);
            }
            int N_total = gridDim.y * BN;
            *(float2*)(C + (size_t)row0 * N_total + col)       = make_float2(v0, v1);
            *(float2*)(C + (size_t)(row0 + 8) * N_total + col) = make_float2(v2, v3);
        }
    }
}

// ---------------- scalar f32x2 GEMM (heads only, N=19) ----------------
template<int BM, int BN, int BK, int TM, int TN, bool RELU, bool NGUARD>
__global__ void __launch_bounds__((BM / TM) * (BN / TN))
gemm_kernel(const float* __restrict__ A, const float* __restrict__ W,
            const float* __restrict__ bias, float* __restrict__ C,
            int N, int K, int ldc) {
    constexpr int THREADS = (BM / TM) * (BN / TN);
    constexpr int BNQ = BN / TN;
    __shared__ __align__(16) float As[BK][BM + 4];
    __shared__ __align__(16) float Ws[BK][BN + 4];

    const int tid = threadIdx.x;
    const int bm = blockIdx.x * BM;
    const int bn = blockIdx.y * BN;
    const int tx = tid % BNQ;
    const int ty = tid / BNQ;

    ull acc2[TM / 2][TN];
#pragma unroll
    for (int i = 0; i < TM / 2; i++)
#pragma unroll
        for (int j = 0; j < TN; j++) acc2[i][j] = 0ull;

    for (int k0 = 0; k0 < K; k0 += BK) {
        constexpr int AV = BM * BK / 4;
#pragma unroll
        for (int i = 0; i < AV / THREADS; i++) {
            int idx = tid + i * THREADS;
            int row = idx / (BK / 4);
            int c4 = idx % (BK / 4);
            float4 v = *(const float4*)(A + (size_t)(bm + row) * K + k0 + c4 * 4);
            As[c4 * 4 + 0][row] = v.x;
            As[c4 * 4 + 1][row] = v.y;
            As[c4 * 4 + 2][row] = v.z;
            As[c4 * 4 + 3][row] = v.w;
        }
        constexpr int WV = BN * BK / 4;
#pragma unroll
        for (int i = 0; i < (WV + THREADS - 1) / THREADS; i++) {
            int idx = tid + i * THREADS;
            if ((WV % THREADS == 0) || idx < WV) {
                int row = idx / (BK / 4);
                int c4 = idx % (BK / 4);
                float4 v;
                if (!NGUARD || (bn + row) < N)
                    v = *(const float4*)(W + (size_t)(bn + row) * K + k0 + c4 * 4);
                else
                    v = make_float4(0.f, 0.f, 0.f, 0.f);
                Ws[c4 * 4 + 0][row] = v.x;
                Ws[c4 * 4 + 1][row] = v.y;
                Ws[c4 * 4 + 2][row] = v.z;
                Ws[c4 * 4 + 3][row] = v.w;
            }
        }
        __syncthreads();
#pragma unroll
        for (int kk = 0; kk < BK; kk++) {
            ull a2[TM / 2];
#pragma unroll
            for (int i2 = 0; i2 < TM / 2; i2++)
                a2[i2] = *(const ull*)&As[kk][ty * TM + 2 * i2];
            float br[TN];
#pragma unroll
            for (int j = 0; j < TN; j++) br[j] = Ws[kk][tx * TN + j];
            ull b2[TN];
#pragma unroll
            for (int j = 0; j < TN; j++) b2[j] = pack2(br[j], br[j]);
#pragma unroll
            for (int i2 = 0; i2 < TM / 2; i2++)
#pragma unroll
                for (int j = 0; j < TN; j++)
                    acc2[i2][j] = ffma2(a2[i2], b2[j], acc2[i2][j]);
        }
        __syncthreads();
    }
#pragma unroll
    for (int j = 0; j < TN; j++) {
        int n = bn + tx * TN + j;
        if (NGUARD && n >= N) continue;
        float bv = bias[n];
#pragma unroll
        for (int i2 = 0; i2 < TM / 2; i2++) {
            float v0, v1;
            unpack2(acc2[i2][j], v0, v1);
            v0 += bv; v1 += bv;
            if (RELU) { v0 = fmaxf(v0, 0.f); v1 = fmaxf(v1, 0.f); }
            C[(size_t)(bm + ty * TM + 2 * i2 + 0) * ldc + n] = v0;
            C[(size_t)(bm + ty * TM + 2 * i2 + 1) * ldc + n] = v1;
        }
    }
}

// ========== persistent tensor-core LSTM ==========
// 128 CTAs x 512 threads (16 warps); CTA owns 8 batch rows for all 256 steps.
// G[512 gates, 8 batch] per step via mma.m16n8k8 (gates=M, batch=N, k=128).
// Warp w computes m-tiles {w, 16+w}:
//   w<8 : i-gates [16w,16w+16) + g-gates (same j)   -> keeps c in registers
//   w>=8: f-gates + o-gates (same j)                -> exchange via 8KB smem
// A-fragments: tiles 0..SM_TILES-1 in smem, rest reg-prefetched from L2.
#define LSTM2_SMEM ((SM_TILES * 2048 + 1024 + 2048) * 4)

__global__ void __launch_bounds__(512, 1)
lstm_tc_kernel(const float* __restrict__ xg, const float* __restrict__ done,
               const float* __restrict__ h0, const float* __restrict__ c0,
               float* __restrict__ hs, const float* __restrict__ frag) {
    extern __shared__ float sm[];
    float* smA = sm;                    // [SM_TILES][16][32][4]
    float* h_s = sm + SM_TILES * 2048;  // [128 j][8 b]  (tf32-rounded, masked)
    float* ex  = h_s + 1024;            // [2][128 j][8 b]  (f, o exchange)

    const int tid  = threadIdx.x;
    const int w    = tid >> 5;
    const int lane = tid & 31;
    const int gg   = lane >> 2;
    const int tg   = lane & 3;
    const int bb0  = blockIdx.x * 8;

    // cooperative load of resident A-fragment tiles
    {
        const uint4* src = (const uint4*)frag;
        uint4* dst = (uint4*)smA;
        for (int i = tid; i < SM_TILES * 512; i += 512) dst[i] = src[i];
    }
    // h_s init: h0 masked by done[0], tf32-rounded
    for (int i = tid; i < 1024; i += 512) {
        int j = i >> 3, b = i & 7;
        float m = 1.f - done[bb0 + b];
        h_s[i] = __uint_as_float(tf32_of(h0[(bb0 + b) * 128 + j] * m));
    }
    __syncthreads();

    const int j0 = 16 * w + gg;         // cell row base (valid w<8)
    const int bA = bb0 + 2 * tg;
    const int bB = bA + 1;

    float c[4] = {0.f, 0.f, 0.f, 0.f};
    if (w < 8) {
        float mA = 1.f - done[bA], mB = 1.f - done[bB];
        c[0] = c0[bA * 128 + j0] * mA;
        c[1] = c0[bB * 128 + j0] * mB;
        c[2] = c0[bA * 128 + j0 + 8] * mA;
        c[3] = c0[bB * 128 + j0 + 8] * mB;
    }

    const int n0 = w * 16 + gg;           // tile0 gate index base
    const int n1 = (16 + w) * 16 + gg;    // tile1
    const uint4* smT0   = (const uint4*)(smA + w * 2048);
    const uint4* smT1   = (const uint4*)(smA + (16 + w) * 2048);
    const uint4* fragT1 = (const uint4*)(frag + (16 + w) * 2048);
    const bool t1smem = (16 + w) < SM_TILES;

    for (int step = 0; step < TT; ++step) {
        // xg for this lane's 8 D-cells (issued early; latency hides under mma)
        const float* xb  = xg + ((size_t)step * BB + bA) * 512;
        const float* xb2 = xb + 512;
        float x0[4], x1[4];
        x0[0] = xb[n0];     x0[1] = xb2[n0];
        x0[2] = xb[n0 + 8]; x0[3] = xb2[n0 + 8];
        x1[0] = xb[n1];     x1[1] = xb2[n1];
        x1[2] = xb[n1 + 8]; x1[3] = xb2[n1 + 8];

        float acc0[4] = {0.f, 0.f, 0.f, 0.f};
        float acc1[4] = {0.f, 0.f, 0.f, 0.f};

        if (t1smem) {
#pragma unroll
            for (int ks = 0; ks < 16; ks++) {
                unsigned b_[2];
                b_[0] = __float_as_uint(h_s[(ks * 8 + tg) * 8 + gg]);
                b_[1] = __float_as_uint(h_s[(ks * 8 + 4 + tg) * 8 + gg]);
                uint4 a0 = smT0[ks * 32 + lane];
                uint4 a1 = smT1[ks * 32 + lane];
                mma_tf32(acc0, (const unsigned*)&a0, b_);
                mma_tf32(acc1, (const unsigned*)&a1, b_);
            }
        } else {
            // batch-issue L2 prefetch of tile1 fragments (MLP=16)
            uint4 pf[16];
#pragma unroll
            for (int ks = 0; ks < 16; ks++) pf[ks] = fragT1[ks * 32 + lane];
#pragma unroll
            for (int ks = 0; ks < 16; ks++) {
                unsigned b_[2];
                b_[0] = __float_as_uint(h_s[(ks * 8 + tg) * 8 + gg]);
                b_[1] = __float_as_uint(h_s[(ks * 8 + 4 + tg) * 8 + gg]);
                uint4 a0 = smT0[ks * 32 + lane];
                mma_tf32(acc0, (const unsigned*)&a0, b_);
                mma_tf32(acc1, (const unsigned*)&pf[ks], b_);
            }
        }

        float ig[4], gt[4];
        if (w >= 8) {
            // f = sigmoid(tile w), o = sigmoid(tile 16+w) -> smem exchange
            int jj = (w - 8) * 16 + gg;
#pragma unroll
            for (int r = 0; r < 4; r++) {
                float fv = sigmoid_f(acc0[r] + x0[r]);
                float ov = sigmoid_f(acc1[r] + x1[r]);
                int j = jj + ((r & 2) ? 8 : 0);
                int b = 2 * tg + (r & 1);
                ex[j * 8 + b]        = fv;
                ex[1024 + j * 8 + b] = ov;
            }
        } else {
#pragma unroll
            for (int r = 0; r < 4; r++) {
                ig[r] = sigmoid_f(acc0[r] + x0[r]);   // i-gate
                gt[r] = tanh_f(acc1[r] + x1[r]);      // g-gate
            }
        }
        __syncthreads();

        if (w < 8) {
            float mA2 = 1.f, mB2 = 1.f;
            if (step + 1 < TT) {
                mA2 = 1.f - done[(size_t)(step + 1) * BB + bA];
                mB2 = 1.f - done[(size_t)(step + 1) * BB + bB];
            }
#pragma unroll
            for (int r = 0; r < 4; r++) {
                int j = j0 + ((r & 2) ? 8 : 0);
                int b = 2 * tg + (r & 1);
                float fv = ex[j * 8 + b];
                float ov = ex[1024 + j * 8 + b];
                c[r] = fv * c[r] + ig[r] * gt[r];
                float hv = ov * tanh_f(c[r]);
                hs[((size_t)step * BB + bb0 + b) * 128 + j] = hv;
                float m = (r & 1) ? mB2 : mA2;
                c[r] *= m;
                h_s[j * 8 + b] = __uint_as_float(tf32_of(hv * m));
            }
        }
        __syncthreads();
    }
}

// ---------------- launch ----------------
extern "C" void kernel_launch(void* const* d_in, const int* in_sizes, int n_in,
                              void* d_out, int out_size) {
    const float* x    = (const float*)d_in[0];
    const float* done = (const float*)d_in[1];
    const float* h0   = (const float*)d_in[2];
    const float* c0   = (const float*)d_in[3];
    const float* W1   = (const float*)d_in[4];
    const float* b1   = (const float*)d_in[5];
    const float* W2   = (const float*)d_in[6];
    const float* b2   = (const float*)d_in[7];
    const float* W3   = (const float*)d_in[8];
    const float* b3   = (const float*)d_in[9];
    const float* Wih  = (const float*)d_in[10];
    const float* Whh  = (const float*)d_in[11];
    const float* bih  = (const float*)d_in[12];
    const float* bhh  = (const float*)d_in[13];
    const float* Wa   = (const float*)d_in[14];
    const float* ba   = (const float*)d_in[15];
    const float* Wc   = (const float*)d_in[16];
    const float* bc   = (const float*)d_in[17];
    float* out = (float*)d_out;

    float *h1, *h2, *h3, *xgp, *hsp, *fragp, *bg, *whd, *bhd;
    cudaGetSymbolAddress((void**)&h1,    g_h1);
    cudaGetSymbolAddress((void**)&h2,    g_h2);
    cudaGetSymbolAddress((void**)&h3,    g_h3);
    cudaGetSymbolAddress((void**)&xgp,   g_xg);
    cudaGetSymbolAddress((void**)&hsp,   g_hs);
    cudaGetSymbolAddress((void**)&fragp, g_WhhFrag);
    cudaGetSymbolAddress((void**)&bg,    g_bg);
    cudaGetSymbolAddress((void**)&whd,   g_Whead);
    cudaGetSymbolAddress((void**)&bhd,   g_bhead);

    static int smem_set = 0;
    if (!smem_set) {
        cudaFuncSetAttribute(lstm_tc_kernel,
                             cudaFuncAttributeMaxDynamicSharedMemorySize,
                             LSTM2_SMEM);
        smem_set = 1;
    }

    prepack_kernel<<<128, 256>>>(Whh, bih, bhh, Wa, ba, Wc, bc);

    // MLP encoder (tf32 tensor cores)
    tf32_gemm<128, 4, 2, true><<<dim3(TB / 128, 1), 256>>>(x,  W1, b1, h1, 128);
    tf32_gemm< 32, 8, 1, true><<<dim3(TB / 128, 1), 256>>>(h1, W2, b2, h2, 128);
    tf32_gemm<128, 4, 2, true><<<dim3(TB / 128, 1), 256>>>(h2, W3, b3, h3, 32);

    // xg = h3 @ Wih^T + (bih+bhh)
    tf32_gemm<256, 2, 4, false><<<dim3(TB / 128, 2), 256>>>(h3, Wih, bg, xgp, 128);

    // Sequential LSTM (tensor-core recurrence)
    lstm_tc_kernel<<<128, 512, LSTM2_SMEM>>>(xgp, done, h0, c0, hsp, fragp);

    // Heads (fp32 scalar, N=19)
    gemm_kernel<128, 32, 32, 8, 2, false, true>
        <<<dim3(TB / 128, 1), 256>>>(hsp, whd, bhd, out, NOUT, 128, NOUT);
}